// round 14
// baseline (speedup 1.0000x reference)
#include <cuda_runtime.h>
#include <cuda_bf16.h>

#define NB 8
#define NT 16384
#define NH 512
#define NC 24
#define NK 100
#define RSTR 131           // ring row stride (128 slots + 3 pad, odd)
#define ESTR 113           // ed row stride (odd)
#define FULL 0xffffffffu

__device__ float g_scores[NB * NC * NT];        // [b][c][t]
__device__ float g_cum[NB * NC * (NT + 1)];     // [b][c][t], cum[0]=0

// ---------------------------------------------------------------------------
// Kernel 1: scores = hs @ W + b, written [b][c][t]
// ---------------------------------------------------------------------------
__global__ __launch_bounds__(256) void gemm_kernel(const float* __restrict__ hs,
                                                   const float* __restrict__ W,
                                                   const float* __restrict__ bias) {
    __shared__ __align__(16) float Wsm[256 * NC];
    __shared__ float bsm[NC];
    const int tid = threadIdx.x;
    const int row = blockIdx.x * 256 + tid;
    if (tid < NC) bsm[tid] = bias[tid];

    float acc[NC];
#pragma unroll
    for (int c = 0; c < NC; ++c) acc[c] = 0.f;
    const float* hp = hs + (size_t)row * NH;

    for (int half = 0; half < 2; ++half) {
        __syncthreads();
        for (int i = tid; i < 256 * NC; i += 256) Wsm[i] = W[half * 256 * NC + i];
        __syncthreads();
        const float* hph = hp + half * 256;
        for (int h = 0; h < 256; h += 4) {
            float4 x = *(const float4*)(hph + h);
#pragma unroll
            for (int j = 0; j < 4; ++j) {
                const float a = (&x.x)[j];
                const float4* wr = (const float4*)(&Wsm[(h + j) * NC]);
#pragma unroll
                for (int q = 0; q < 6; ++q) {
                    float4 wv = wr[q];
                    acc[q * 4 + 0] = fmaf(a, wv.x, acc[q * 4 + 0]);
                    acc[q * 4 + 1] = fmaf(a, wv.y, acc[q * 4 + 1]);
                    acc[q * 4 + 2] = fmaf(a, wv.z, acc[q * 4 + 2]);
                    acc[q * 4 + 3] = fmaf(a, wv.w, acc[q * 4 + 3]);
                }
            }
        }
    }
    const int b = row / NT;
    const int t = row % NT;
#pragma unroll
    for (int c = 0; c < NC; ++c)
        g_scores[((size_t)(b * NC + c)) * NT + t] = acc[c] + bsm[c];
}

// ---------------------------------------------------------------------------
// Kernel 2: per-(b,c) prefix sum.
// ---------------------------------------------------------------------------
__global__ __launch_bounds__(32) void cumsum_kernel() {
    const int bc = blockIdx.x;
    const int lane = threadIdx.x;
    const float* sp = g_scores + (size_t)bc * NT;
    float* cp = g_cum + (size_t)bc * (NT + 1);
    if (lane == 0) cp[0] = 0.f;
    float carry = 0.f;
#pragma unroll 2
    for (int base = 0; base < NT; base += 32) {
        float v = sp[base + lane];
#pragma unroll
        for (int off = 1; off < 32; off <<= 1) {
            float n = __shfl_up_sync(FULL, v, off);
            if (lane >= off) v += n;
        }
        cp[base + lane + 1] = carry + v;
        carry += __shfl_sync(FULL, v, 31);
    }
}

// ---------------------------------------------------------------------------
// Kernel 3: warp-specialized scan. 128 threads: warp0 = mix (lane=channel),
// warps 1-3 = externals (precompute far-window dots X for the NEXT block).
// Ring E[s,c]=exp(msg-cum-R_c): single-width 128 slots/channel, rescaled
// (live span only) every 8-step boundary by all threads (pow-2, from sc_sm).
// ---------------------------------------------------------------------------
__global__ __launch_bounds__(128) void scan_kernel(const float* __restrict__ trans,
                                                   const float* __restrict__ dur,
                                                   const int* __restrict__ lengths,
                                                   float* __restrict__ out) {
    __shared__ float ring[NC * RSTR];
    __shared__ float ed_sm[NC * ESTR];
    __shared__ float X_sm[2][8][32];
    __shared__ float Pstage[8][32];
    __shared__ float sc_sm[32];

    const int tid = threadIdx.x;
    const int warp = tid >> 5;
    const int lane = tid & 31;
    const int b = blockIdx.x;
    const float LN2 = 0.6931471805599453f;

    for (int i = tid; i < NC * RSTR; i += 128) ring[i] = 0.f;
    for (int i = tid; i < NC * ESTR; i += 128) {
        const int c = i / ESTR, k = i % ESTR;
        ed_sm[i] = (k >= 1 && k <= NK) ? __expf(dur[(k - 1) * NC + c]) : 0.f;
    }
    for (int i = tid; i < 8 * 32; i += 128) {
        X_sm[0][i >> 5][i & 31] = 0.f;
        X_sm[1][i >> 5][i & 31] = 0.f;
        if (i < 32) sc_sm[i] = 1.f;
    }
    if (tid < NC) ring[tid * RSTR] = 1.f;          // E[0] = 1
    __syncthreads();

    int len = lengths[b];
    len = len < 1 ? 1 : (len > NT ? NT : len);

    // ---- mix-warp state ----
    const int cm = (lane < NC) ? lane : NC - 1;
    const float* cumb = g_cum + (size_t)(b * NC + cm) * (NT + 1);
    float etr[NC], edk[15];
    float Eb[8], P[8], cumv[9], cumnext[9], Xr[8];
    float R = 0.f, shift = 0.f, beta = 0.f, rbeta = 0.f, sc = 1.f, rsc = 1.f;
    if (warp == 0) {
#pragma unroll
        for (int cp = 0; cp < NC; ++cp) etr[cp] = __expf(trans[cp * NC + cm]);
#pragma unroll
        for (int i = 0; i < 15; ++i) edk[i] = __expf(dur[i * NC + cm]);
#pragma unroll
        for (int i = 0; i < 8; ++i) { P[i] = 0.f; Eb[i] = 0.f; }
        P[7] = 1.f;                                 // E[0]
#pragma unroll
        for (int i = 0; i < 9; ++i) { int idx = 1 + i; cumv[i] = cumb[idx]; }
#pragma unroll
        for (int i = 0; i < 9; ++i) { int idx = 9 + i; idx = idx > NT ? NT : idx; cumnext[i] = cumb[idx]; }
        beta = __expf(cumv[0]);
        rbeta = __expf(-cumv[0]);
    }
    // ---- ext-warp constants ----
    const int l = tid - 32;                         // 0..95 for warps 1-3
    const int ce = (l >= 0) ? (l % NC) : 0;
    const int j0 = (l >= 0) ? 2 * (l / NC) : 0;
    const float* rrow = ring + ce * RSTR;
    const float* erow = ed_sm + ce * ESTR;

#pragma unroll 1
    for (int n = 0;; ++n) {
        const int T = 1 + 8 * n;
        if (n > 0) {
            __syncthreads();                        // A: Pstage+sc_sm published; X done
            // cooperative rescale of live slots s in [T-92, T-9], + insert E[T-8..T-1]
            for (int q = tid; q < 84 * NC; q += 128) {
                const int c = q / 84;
                const int i = q - c * 84;
                const int slot = (T - 92 + i) & 127;
                ring[c * RSTR + slot] *= sc_sm[c];
            }
            for (int q = tid; q < 8 * NC; q += 128) {
                const int c = q >> 3;
                const int i = q & 7;
                ring[c * RSTR + ((T - 8 + i) & 127)] = Pstage[i][c] * sc_sm[c];
            }
            __syncthreads();                        // B
        }

        if (warp == 0) {
            // ================= MIX =================
            if (n > 0) {
                R += (float)((__float_as_int(sc) >> 23) == 0 ? 0 : 0); // no-op keep
                R += 0.f;
                // boundary fixups (de encoded in sc/rsc computed last block)
                beta *= rsc;
                rbeta *= sc;
#pragma unroll
                for (int i = 0; i < 8; ++i) P[i] = Eb[i] * sc;
#pragma unroll
                for (int i = 0; i < 9; ++i) cumv[i] = cumnext[i];
#pragma unroll
                for (int j = 0; j < 8; ++j) Xr[j] = X_sm[n & 1][j][lane] * sc;
                // prefetch next block's cum
#pragma unroll
                for (int i = 0; i < 9; ++i) {
                    int idx = T + 8 + i; idx = idx > NT ? NT : idx;
                    cumnext[i] = cumb[idx];
                }
            } else {
#pragma unroll
                for (int j = 0; j < 8; ++j) Xr[j] = X_sm[0][j][lane];
            }

#pragma unroll
            for (int j = 0; j < 8; ++j) {
                const int t = T + j;
                float D = Xr[j];
#pragma unroll
                for (int kk = 1; kk <= 15; ++kk) {
                    if (kk <= 8 + j) {
                        const float Ev = (kk <= j) ? Eb[j - kk] : P[8 + j - kk];
                        D = fmaf(Ev, edk[kk - 1], D);
                    }
                }
                const float u = D * beta;           // exp(alpha_c - shift)
                float w0 = 0.f, w1 = 0.f, w2 = 0.f, w3 = 0.f;
#pragma unroll
                for (int cp = 0; cp < NC; cp += 4) {
                    w0 = fmaf(__shfl_sync(FULL, u, cp + 0), etr[cp + 0], w0);
                    w1 = fmaf(__shfl_sync(FULL, u, cp + 1), etr[cp + 1], w1);
                    w2 = fmaf(__shfl_sync(FULL, u, cp + 2), etr[cp + 2], w2);
                    w3 = fmaf(__shfl_sync(FULL, u, cp + 3), etr[cp + 3], w3);
                }
                const float w = (w0 + w1) + (w2 + w3);
                const float Et = w * rbeta;         // E[t]
                Eb[j] = Et;
                Pstage[j][lane] = Et;

                if (t == len) {
                    float su = (lane < NC) ? u : 0.f;
#pragma unroll
                    for (int off = 16; off > 0; off >>= 1)
                        su += __shfl_xor_sync(FULL, su, off);
                    if (lane == 0) out[b] = shift + __logf(fmaxf(su, 1e-37f));
                }

                // shift feedback (uniform; pure ALU)
                const float u0 = __shfl_sync(FULL, u, 0);
                int e0 = (__float_as_int(u0) >> 23) & 255;
                int ds = (e0 == 0) ? -30 : (e0 - 127);
                ds = ds < -30 ? -30 : (ds > 30 ? 30 : ds);
                shift = fmaf((float)ds, LN2, shift);

                const float xn = cumv[j + 1] + R - shift;
                beta = __expf(xn);
                rbeta = __expf(-xn);
            }
            // prepare next boundary: anchor from Eb[7]
            {
                int eb = (__float_as_int(Eb[7]) >> 23) & 255;
                if (eb == 0) eb = 1;
                int de = eb - 82;                   // Eb[7]*2^{-de} ~ 2^{-45}
                de = de < -100 ? -100 : (de > 120 ? 120 : de);
                sc = __int_as_float((127 - de) << 23);
                rsc = __int_as_float((127 + de) << 23);
                R += (float)de * LN2;               // applied to NEXT block's values
                sc_sm[lane] = sc;
            }
        } else {
            // ================= EXT: X for block n+1 =================
            const int Tn = T + 8;
            const int s0 = Tn - 100;
            const int nb = (n + 1) & 1;
            float a0 = 0.f, a1 = 0.f, b0 = 0.f, b1 = 0.f;
#pragma unroll
            for (int i = 0; i < 92; i += 2) {
                const float E1 = rrow[(s0 + i) & 127];
                const float E2 = rrow[(s0 + i + 1) & 127];
                a0 = fmaf(E1, erow[100 + j0 - i], a0);
                b0 = fmaf(E1, erow[101 + j0 - i], b0);
                a1 = fmaf(E2, erow[99 + j0 - i], a1);
                b1 = fmaf(E2, erow[100 + j0 - i], b1);
            }
            X_sm[nb][j0][ce] = a0 + a1;
            X_sm[nb][j0 + 1][ce] = b0 + b1;
        }
        if (T + 7 >= len) break;
    }
}

// ---------------------------------------------------------------------------
extern "C" void kernel_launch(void* const* d_in, const int* in_sizes, int n_in,
                              void* d_out, int out_size) {
    const float* hs    = (const float*)d_in[0];   // [B,T,H]
    const float* W     = (const float*)d_in[1];   // [H,C]
    const float* bias  = (const float*)d_in[2];   // [C]
    const float* trans = (const float*)d_in[3];   // [C,C]
    const float* dur   = (const float*)d_in[4];   // [K,C]
    const int*   len   = (const int*)d_in[5];     // [B]
    float* out = (float*)d_out;

    gemm_kernel<<<(NB * NT) / 256, 256>>>(hs, W, bias);
    cumsum_kernel<<<NB * NC, 32>>>();
    scan_kernel<<<NB, 128>>>(trans, dur, len, out);
}

// round 16
// speedup vs baseline: 4.6959x; 4.6959x over previous
#include <cuda_runtime.h>
#include <cuda_bf16.h>

#define NB 8
#define NT 16384
#define NH 512
#define NC 24
#define NK 100
#define RST 264            // ring stride in floats (256 live + 8 pad)
#define CHUNK 2048
#define NCH 8
#define MFIX 1024
#define FULL 0xffffffffu

// Scratch (device globals; no allocation allowed)
__device__ float g_scores[NB * NC * NT];        // [b][c][t]
__device__ float g_cum[NB * NC * (NT + 1)];     // [b][c][t], cum[0]=0
__device__ float g_stateE[NB * NCH * NC * 128]; // end-window rings
__device__ float g_stateR[NB * NCH * NC];       // per-channel anchors
__device__ float g_stateS[NB * NCH];            // shift ledgers
__device__ float g_lsem[NB * NCH];              // comp LSE at local step MFIX
__device__ float g_C[NB * NCH];                 // per-chunk scalar corrections
__device__ float g_outA[NB];
__device__ int   g_outP[NB];

// ---------------------------------------------------------------------------
// Kernel 1: scores[b,t,c] = hidden[b,t,:] @ W[:,c] + bias[c], written [b][c][t]
// ---------------------------------------------------------------------------
__global__ __launch_bounds__(256) void gemm_kernel(const float* __restrict__ hs,
                                                   const float* __restrict__ W,
                                                   const float* __restrict__ bias) {
    __shared__ __align__(16) float Wsm[256 * NC];
    __shared__ float bsm[NC];
    const int tid = threadIdx.x;
    const int row = blockIdx.x * 256 + tid;
    if (tid < NC) bsm[tid] = bias[tid];

    float acc[NC];
#pragma unroll
    for (int c = 0; c < NC; ++c) acc[c] = 0.f;
    const float* hp = hs + (size_t)row * NH;

    for (int half = 0; half < 2; ++half) {
        __syncthreads();
        for (int i = tid; i < 256 * NC; i += 256) Wsm[i] = W[half * 256 * NC + i];
        __syncthreads();
        const float* hph = hp + half * 256;
        for (int h = 0; h < 256; h += 4) {
            float4 x = *(const float4*)(hph + h);
#pragma unroll
            for (int j = 0; j < 4; ++j) {
                const float a = (&x.x)[j];
                const float4* wr = (const float4*)(&Wsm[(h + j) * NC]);
#pragma unroll
                for (int q = 0; q < 6; ++q) {
                    float4 wv = wr[q];
                    acc[q * 4 + 0] = fmaf(a, wv.x, acc[q * 4 + 0]);
                    acc[q * 4 + 1] = fmaf(a, wv.y, acc[q * 4 + 1]);
                    acc[q * 4 + 2] = fmaf(a, wv.z, acc[q * 4 + 2]);
                    acc[q * 4 + 3] = fmaf(a, wv.w, acc[q * 4 + 3]);
                }
            }
        }
    }
    const int b = row / NT;
    const int t = row % NT;
#pragma unroll
    for (int c = 0; c < NC; ++c)
        g_scores[((size_t)(b * NC + c)) * NT + t] = acc[c] + bsm[c];
}

// ---------------------------------------------------------------------------
// Kernel 2: per-(b,c) inclusive prefix -> g_cum[b][c][1..T], g_cum[..][0]=0.
// ---------------------------------------------------------------------------
__global__ __launch_bounds__(32) void cumsum_kernel() {
    const int bc = blockIdx.x;
    const int lane = threadIdx.x;
    const float* sp = g_scores + (size_t)bc * NT;
    float* cp = g_cum + (size_t)bc * (NT + 1);
    if (lane == 0) cp[0] = 0.f;
    float carry = 0.f;
#pragma unroll 2
    for (int base = 0; base < NT; base += 32) {
        float v = sp[base + lane];
#pragma unroll
        for (int off = 1; off < 32; off <<= 1) {
            float n = __shfl_up_sync(FULL, v, off);
            if (lane >= off) v += n;
        }
        cp[base + lane + 1] = carry + v;
        carry += __shfl_sync(FULL, v, 31);
    }
}

// ---------------------------------------------------------------------------
// Chunked scan core (R11 inner loop). PHASE 1: LEVELED delta-init comp run
// over CHUNK steps (R_c = -cum_c(Tstart) => restart msg'[Tstart]=0, all
// values O(1); chunk 0 == true init). PHASE 2: rerun of MFIX steps from
// chunk p-1's stored end state; C_p = rerun LSE - comp LSE telescopes the
// rank-1 offsets (Perron-Frobenius).
// ---------------------------------------------------------------------------
template<int PHASE>
__global__ __launch_bounds__(192) void scan_kernel(const float* __restrict__ trans,
                                                   const float* __restrict__ dur,
                                                   const int* __restrict__ lengths) {
    __shared__ __align__(16) float ring[NC * RST];
    __shared__ float u_sm[2][NC];

    const int tid = threadIdx.x;
    const int warp = tid >> 5;
    const int lane = tid & 31;
    const int grp = lane >> 3;
    const int sl = lane & 7;
    const int c = warp * 4 + grp;
    const int laneBase = lane & 24;
    const float LN2 = 0.6931471805599453f;

    int b, p;
    if (PHASE == 1) { b = blockIdx.x >> 3; p = blockIdx.x & 7; }
    else            { b = blockIdx.x / (NCH - 1); p = 1 + blockIdx.x % (NCH - 1); }

    int len = lengths[b];
    len = len < 1 ? 1 : (len > NT ? NT : len);
    const int Tstart = p * CHUNK;
    if (Tstart >= len) return;
    const int L = (PHASE == 1) ? CHUNK : MFIX;
    const int Tend = Tstart + L;
    const int lenLoc = (len - Tstart < L) ? (len - Tstart) : L;

    if (PHASE == 1) {
        for (int i = tid; i < NC * RST; i += 192) {
            const int x = i % RST;
            ring[i] = (x == 0 || x == 128) ? 1.f : 0.f;
        }
    } else {
        const float* src = g_stateE + (size_t)(b * NCH + (p - 1)) * NC * 128;
        for (int i = tid; i < NC * 128; i += 192) {
            const int cc = i >> 7, s = i & 127;
            const float v = src[i];
            ring[cc * RST + s] = v;
            ring[cc * RST + s + 128] = v;
        }
    }

    const float ed1s = __expf(dur[0 * NC + c]);
    float edt[13];
#pragma unroll
    for (int i = 0; i < 13; ++i) {
        const int k = 2 + 13 * sl + i;
        edt[i] = (k <= NK) ? __expf(dur[(k - 1) * NC + c]) : 0.f;
    }
    const float etr0 = __expf(trans[(3 * sl + 0) * NC + c]);
    const float etr1 = __expf(trans[(3 * sl + 1) * NC + c]);
    const float etr2 = __expf(trans[(3 * sl + 2) * NC + c]);
    __syncthreads();

    const float* cumb = g_cum + (size_t)(b * NC + c) * (NT + 1);
    float* ringc = ring + c * RST;

    float R, shift, tailD, Et1;
    if (PHASE == 1) {
        R = -cumb[Tstart];            // LEVELED restart: msg'[Tstart] = 0
        shift = 0.f; tailD = 0.f; Et1 = 1.f;
    } else {
        R = g_stateR[(b * NCH + (p - 1)) * NC + c];
        shift = g_stateS[b * NCH + (p - 1)];
        Et1 = ringc[0];               // E at s = Tstart (Tstart % 128 == 0)
        // tail for first step t = Tstart+1 (in-loop pattern with t := Tstart)
        const float* pp = ringc + (((Tstart - 1 - 13 * sl) & 127) + 116);
        float ta = pp[12] * edt[0];
        float tb2 = pp[11] * edt[1];
        float tcc = pp[10] * edt[2];
        ta = fmaf(pp[9], edt[3], ta);
        tb2 = fmaf(pp[8], edt[4], tb2);
        tcc = fmaf(pp[7], edt[5], tcc);
        ta = fmaf(pp[6], edt[6], ta);
        tb2 = fmaf(pp[5], edt[7], tb2);
        tcc = fmaf(pp[4], edt[8], tcc);
        ta = fmaf(pp[3], edt[9], ta);
        tb2 = fmaf(pp[2], edt[10], tb2);
        tcc = fmaf(pp[1], edt[11], tcc);
        ta = fmaf(pp[0], edt[12], ta);
        float tb = ta + tb2 + tcc;
#pragma unroll
        for (int off = 4; off > 0; off >>= 1)
            tb += __shfl_xor_sync(FULL, tb, off);
        tailD = tb;
    }

    float cumA[4], cumB[4];
#pragma unroll
    for (int m = 0; m < 4; ++m) cumA[m] = cumb[Tstart + 2 + 8 * m + sl];
    const float x1 = cumb[Tstart + 1] + R - shift;
    float beta = __expf(x1);
    float rbeta = __expf(-x1);

#pragma unroll 1
    for (int lt0 = 1; lt0 <= L; lt0 += 32) {
        if (lt0 + 32 <= L) {
#pragma unroll
            for (int m = 0; m < 4; ++m) {
                int idx = Tstart + lt0 + 33 + 8 * m + sl;
                idx = idx > NT ? NT : idx;
                cumB[m] = cumb[idx];
            }
        }
#pragma unroll 1
        for (int g8 = 0; g8 < 4; ++g8) {
            if (lt0 > 1 || g8 > 0) {
                __syncwarp();
                int eb = (__float_as_int(Et1) >> 23) & 255;
                if (eb == 0) eb = 1;
                int de = eb - 82;
                de = de < -100 ? -100 : (de > 120 ? 120 : de);
                const float sc = __int_as_float((127 - de) << 23);
                const float rsc = __int_as_float((127 + de) << 23);
#pragma unroll
                for (int m = 0; m < 32; ++m) ringc[sl + 8 * m] *= sc;
                Et1 *= sc;
                tailD *= sc;
                R += (float)de * LN2;
                beta *= rsc;
                rbeta *= sc;
                __syncwarp();
            }
            const float cumCur = cumA[g8];
#pragma unroll
            for (int q = 0; q < 8; ++q) {
                const int lt = lt0 + g8 * 8 + q;
                const int t = Tstart + lt;
                const int par = lt & 1;

                const float D = fmaf(Et1, ed1s, tailD);
                const float u = D * beta;        // exp(alpha_c - shift)
                if (sl == 0) u_sm[par][c] = u;
                __syncthreads();

                const float* ub = u_sm[par];
                const float uv0 = ub[3 * sl + 0];
                const float uv1 = ub[3 * sl + 1];
                const float uv2 = ub[3 * sl + 2];
                float w = fmaf(uv2, etr2, fmaf(uv1, etr1, uv0 * etr0));

                const float* pp = ringc + (((t - 1 - 13 * sl) & 127) + 116);
                float ta = pp[12] * edt[0];
                float tb2 = pp[11] * edt[1];
                float tcc = pp[10] * edt[2];
                ta = fmaf(pp[9], edt[3], ta);
                tb2 = fmaf(pp[8], edt[4], tb2);
                tcc = fmaf(pp[7], edt[5], tcc);
                ta = fmaf(pp[6], edt[6], ta);
                tb2 = fmaf(pp[5], edt[7], tb2);
                tcc = fmaf(pp[4], edt[8], tcc);
                ta = fmaf(pp[3], edt[9], ta);
                tb2 = fmaf(pp[2], edt[10], tb2);
                tcc = fmaf(pp[1], edt[11], tcc);
                ta = fmaf(pp[0], edt[12], ta);
                float tb = ta + tb2 + tcc;

#pragma unroll
                for (int off = 4; off > 0; off >>= 1) {
                    w  += __shfl_xor_sync(FULL, w, off);
                    tb += __shfl_xor_sync(FULL, tb, off);
                }

                const float Et = w * rbeta;
                const int slot = t & 127;
                if (sl == 0) {
                    ringc[slot] = Et;
                    ringc[slot + 128] = Et;
                }

                if (lt == MFIX || t == len) {
                    float su = uv0 + uv1 + uv2;
#pragma unroll
                    for (int off = 4; off > 0; off >>= 1)
                        su += __shfl_xor_sync(FULL, su, off);
                    if (tid == 0) {
                        const float val = shift + __logf(fmaxf(su, 1e-37f));
                        if (PHASE == 1) {
                            if (lt == MFIX) g_lsem[b * NCH + p] = val;
                            if (t == len && (p == 0 || lt > MFIX)) {
                                g_outA[b] = val;
                                g_outP[b] = p;
                            }
                        } else {
                            if (lt == MFIX) g_C[b * NCH + p] = val - g_lsem[b * NCH + p];
                            if (t == len) {
                                g_outA[b] = val;
                                g_outP[b] = p - 1;
                            }
                        }
                    }
                }

                const float u0 = __shfl_sync(FULL, uv0, 0);
                int e0 = (__float_as_int(u0) >> 23) & 255;
                int ds = (e0 == 0) ? -30 : (e0 - 127);
                ds = ds < -30 ? -30 : (ds > 30 ? 30 : ds);
                shift = fmaf((float)ds, LN2, shift);

                const float crN = __shfl_sync(FULL, cumCur, laneBase + q) + R;
                const float xn = crN - shift;
                beta = __expf(xn);
                rbeta = __expf(-xn);

                Et1 = Et;
                tailD = tb;
            }
        }
        if (lt0 + 31 >= lenLoc) break;
#pragma unroll
        for (int m = 0; m < 4; ++m) cumA[m] = cumB[m];
    }

    if (PHASE == 1 && p < NCH - 1 && len > Tend) {
        __syncthreads();
        float* dst = g_stateE + (size_t)(b * NCH + p) * NC * 128;
        for (int i = tid; i < NC * 128; i += 192)
            dst[i] = ring[(i >> 7) * RST + (i & 127)];
        if (sl == 0) g_stateR[(b * NCH + p) * NC + c] = R;
        if (tid == 0) g_stateS[b * NCH + p] = shift;
    }
}

// ---------------------------------------------------------------------------
// Kernel 4: prefix the corrections and emit final partitions.
// ---------------------------------------------------------------------------
__global__ void fix_kernel(float* __restrict__ out) {
    const int b = threadIdx.x;
    if (b < NB) {
        float d = 0.f;
        const int P = g_outP[b];
        for (int q = 1; q <= P; ++q) d += g_C[b * NCH + q];
        out[b] = g_outA[b] + d;
    }
}

// ---------------------------------------------------------------------------
extern "C" void kernel_launch(void* const* d_in, const int* in_sizes, int n_in,
                              void* d_out, int out_size) {
    const float* hs    = (const float*)d_in[0];   // [B,T,H]
    const float* W     = (const float*)d_in[1];   // [H,C]
    const float* bias  = (const float*)d_in[2];   // [C]
    const float* trans = (const float*)d_in[3];   // [C,C]
    const float* dur   = (const float*)d_in[4];   // [K,C]
    const int*   len   = (const int*)d_in[5];     // [B]
    float* out = (float*)d_out;

    gemm_kernel<<<(NB * NT) / 256, 256>>>(hs, W, bias);
    cumsum_kernel<<<NB * NC, 32>>>();
    scan_kernel<1><<<NB * NCH, 192>>>(trans, dur, len);
    scan_kernel<2><<<NB * (NCH - 1), 192>>>(trans, dur, len);
    fix_kernel<<<1, 32>>>(out);
}

// round 17
// speedup vs baseline: 7.4107x; 1.5781x over previous
#include <cuda_runtime.h>
#include <cuda_bf16.h>

#define NB 8
#define NT 16384
#define NH 512
#define NC 24
#define NK 100
#define RST 264            // ring stride in floats (256 live + 8 pad)
#define CHUNK 1024
#define NCH 16
#define MFIX 512
#define FULL 0xffffffffu

// Scratch (device globals; no allocation allowed)
__device__ float g_scores[NB * NC * NT];        // [b][c][t]
__device__ float g_cum[NB * NC * (NT + 1)];     // [b][c][t], cum[0]=0
__device__ float g_stateE[NB * NCH * NC * 128]; // end-window rings
__device__ float g_stateR[NB * NCH * NC];       // per-channel anchors
__device__ float g_stateS[NB * NCH];            // shift ledgers
__device__ float g_lsem[NB * NCH];              // comp LSE at local step MFIX
__device__ float g_C[NB * NCH];                 // per-chunk scalar corrections
__device__ float g_outA[NB];
__device__ int   g_outP[NB];

// ---------------------------------------------------------------------------
// Kernel 1: scores = hs @ W + b, written [b][c][t]. 4 rows per thread so the
// 6 W LDS.128 per h serve 96 FFMA (was 24) -> smem-throughput no longer binds.
// ---------------------------------------------------------------------------
__global__ __launch_bounds__(256) void gemm_kernel(const float* __restrict__ hs,
                                                   const float* __restrict__ W,
                                                   const float* __restrict__ bias) {
    __shared__ __align__(16) float Wsm[256 * NC];   // 24 KB (half of W)
    __shared__ float bsm[NC];
    const int tid = threadIdx.x;
    const int rowbase = blockIdx.x * 1024;
    if (tid < NC) bsm[tid] = bias[tid];

    float acc0[NC], acc1[NC], acc2[NC], acc3[NC];
#pragma unroll
    for (int c = 0; c < NC; ++c) { acc0[c] = 0.f; acc1[c] = 0.f; acc2[c] = 0.f; acc3[c] = 0.f; }

    const int r0 = rowbase + tid;
    const float* hp0 = hs + (size_t)r0 * NH;
    const float* hp1 = hp0 + (size_t)256 * NH;
    const float* hp2 = hp0 + (size_t)512 * NH;
    const float* hp3 = hp0 + (size_t)768 * NH;

    for (int half = 0; half < 2; ++half) {
        __syncthreads();
        for (int i = tid; i < 256 * NC; i += 256) Wsm[i] = W[half * 256 * NC + i];
        __syncthreads();
        const int hbase = half * 256;
        for (int h = 0; h < 256; h += 4) {
            float4 x0 = *(const float4*)(hp0 + hbase + h);
            float4 x1 = *(const float4*)(hp1 + hbase + h);
            float4 x2 = *(const float4*)(hp2 + hbase + h);
            float4 x3 = *(const float4*)(hp3 + hbase + h);
#pragma unroll
            for (int j = 0; j < 4; ++j) {
                const float a0 = (&x0.x)[j];
                const float a1 = (&x1.x)[j];
                const float a2 = (&x2.x)[j];
                const float a3 = (&x3.x)[j];
                const float4* wr = (const float4*)(&Wsm[(h + j) * NC]);
#pragma unroll
                for (int q = 0; q < 6; ++q) {
                    float4 wv = wr[q];
                    acc0[q * 4 + 0] = fmaf(a0, wv.x, acc0[q * 4 + 0]);
                    acc0[q * 4 + 1] = fmaf(a0, wv.y, acc0[q * 4 + 1]);
                    acc0[q * 4 + 2] = fmaf(a0, wv.z, acc0[q * 4 + 2]);
                    acc0[q * 4 + 3] = fmaf(a0, wv.w, acc0[q * 4 + 3]);
                    acc1[q * 4 + 0] = fmaf(a1, wv.x, acc1[q * 4 + 0]);
                    acc1[q * 4 + 1] = fmaf(a1, wv.y, acc1[q * 4 + 1]);
                    acc1[q * 4 + 2] = fmaf(a1, wv.z, acc1[q * 4 + 2]);
                    acc1[q * 4 + 3] = fmaf(a1, wv.w, acc1[q * 4 + 3]);
                    acc2[q * 4 + 0] = fmaf(a2, wv.x, acc2[q * 4 + 0]);
                    acc2[q * 4 + 1] = fmaf(a2, wv.y, acc2[q * 4 + 1]);
                    acc2[q * 4 + 2] = fmaf(a2, wv.z, acc2[q * 4 + 2]);
                    acc2[q * 4 + 3] = fmaf(a2, wv.w, acc2[q * 4 + 3]);
                    acc3[q * 4 + 0] = fmaf(a3, wv.x, acc3[q * 4 + 0]);
                    acc3[q * 4 + 1] = fmaf(a3, wv.y, acc3[q * 4 + 1]);
                    acc3[q * 4 + 2] = fmaf(a3, wv.z, acc3[q * 4 + 2]);
                    acc3[q * 4 + 3] = fmaf(a3, wv.w, acc3[q * 4 + 3]);
                }
            }
        }
    }

    const int b = r0 / NT;                 // block of 1024 rows stays in one b
    const int t = r0 % NT;
#pragma unroll
    for (int c = 0; c < NC; ++c) {
        float* sp = g_scores + ((size_t)(b * NC + c)) * NT + t;
        sp[0]   = acc0[c] + bsm[c];
        sp[256] = acc1[c] + bsm[c];
        sp[512] = acc2[c] + bsm[c];
        sp[768] = acc3[c] + bsm[c];
    }
}

// ---------------------------------------------------------------------------
// Kernel 2: per-(b,c) inclusive prefix -> g_cum[b][c][1..T], g_cum[..][0]=0.
// ---------------------------------------------------------------------------
__global__ __launch_bounds__(32) void cumsum_kernel() {
    const int bc = blockIdx.x;
    const int lane = threadIdx.x;
    const float* sp = g_scores + (size_t)bc * NT;
    float* cp = g_cum + (size_t)bc * (NT + 1);
    if (lane == 0) cp[0] = 0.f;
    float carry = 0.f;
#pragma unroll 2
    for (int base = 0; base < NT; base += 32) {
        float v = sp[base + lane];
#pragma unroll
        for (int off = 1; off < 32; off <<= 1) {
            float n = __shfl_up_sync(FULL, v, off);
            if (lane >= off) v += n;
        }
        cp[base + lane + 1] = carry + v;
        carry += __shfl_sync(FULL, v, 31);
    }
}

// ---------------------------------------------------------------------------
// Chunked scan core (identical to R15's passing version; only CHUNK/NCH/MFIX
// changed). PHASE 1: leveled delta-init comp run (R_c = -cum_c(Tstart)).
// PHASE 2: rerun of MFIX steps from chunk p-1's end state; C_p telescopes.
// ---------------------------------------------------------------------------
template<int PHASE>
__global__ __launch_bounds__(192) void scan_kernel(const float* __restrict__ trans,
                                                   const float* __restrict__ dur,
                                                   const int* __restrict__ lengths) {
    __shared__ __align__(16) float ring[NC * RST];
    __shared__ float u_sm[2][NC];

    const int tid = threadIdx.x;
    const int warp = tid >> 5;
    const int lane = tid & 31;
    const int grp = lane >> 3;
    const int sl = lane & 7;
    const int c = warp * 4 + grp;
    const int laneBase = lane & 24;
    const float LN2 = 0.6931471805599453f;

    int b, p;
    if (PHASE == 1) { b = blockIdx.x >> 4; p = blockIdx.x & 15; }
    else            { b = blockIdx.x / (NCH - 1); p = 1 + blockIdx.x % (NCH - 1); }

    int len = lengths[b];
    len = len < 1 ? 1 : (len > NT ? NT : len);
    const int Tstart = p * CHUNK;
    if (Tstart >= len) return;
    const int L = (PHASE == 1) ? CHUNK : MFIX;
    const int Tend = Tstart + L;
    const int lenLoc = (len - Tstart < L) ? (len - Tstart) : L;

    if (PHASE == 1) {
        for (int i = tid; i < NC * RST; i += 192) {
            const int x = i % RST;
            ring[i] = (x == 0 || x == 128) ? 1.f : 0.f;
        }
    } else {
        const float* src = g_stateE + (size_t)(b * NCH + (p - 1)) * NC * 128;
        for (int i = tid; i < NC * 128; i += 192) {
            const int cc = i >> 7, s = i & 127;
            const float v = src[i];
            ring[cc * RST + s] = v;
            ring[cc * RST + s + 128] = v;
        }
    }

    const float ed1s = __expf(dur[0 * NC + c]);
    float edt[13];
#pragma unroll
    for (int i = 0; i < 13; ++i) {
        const int k = 2 + 13 * sl + i;
        edt[i] = (k <= NK) ? __expf(dur[(k - 1) * NC + c]) : 0.f;
    }
    const float etr0 = __expf(trans[(3 * sl + 0) * NC + c]);
    const float etr1 = __expf(trans[(3 * sl + 1) * NC + c]);
    const float etr2 = __expf(trans[(3 * sl + 2) * NC + c]);
    __syncthreads();

    const float* cumb = g_cum + (size_t)(b * NC + c) * (NT + 1);
    float* ringc = ring + c * RST;

    float R, shift, tailD, Et1;
    if (PHASE == 1) {
        R = -cumb[Tstart];            // leveled restart: msg'[Tstart] = 0
        shift = 0.f; tailD = 0.f; Et1 = 1.f;
    } else {
        R = g_stateR[(b * NCH + (p - 1)) * NC + c];
        shift = g_stateS[b * NCH + (p - 1)];
        Et1 = ringc[0];               // E at s = Tstart (Tstart % 128 == 0)
        const float* pp = ringc + (((Tstart - 1 - 13 * sl) & 127) + 116);
        float ta = pp[12] * edt[0];
        float tb2 = pp[11] * edt[1];
        float tcc = pp[10] * edt[2];
        ta = fmaf(pp[9], edt[3], ta);
        tb2 = fmaf(pp[8], edt[4], tb2);
        tcc = fmaf(pp[7], edt[5], tcc);
        ta = fmaf(pp[6], edt[6], ta);
        tb2 = fmaf(pp[5], edt[7], tb2);
        tcc = fmaf(pp[4], edt[8], tcc);
        ta = fmaf(pp[3], edt[9], ta);
        tb2 = fmaf(pp[2], edt[10], tb2);
        tcc = fmaf(pp[1], edt[11], tcc);
        ta = fmaf(pp[0], edt[12], ta);
        float tb = ta + tb2 + tcc;
#pragma unroll
        for (int off = 4; off > 0; off >>= 1)
            tb += __shfl_xor_sync(FULL, tb, off);
        tailD = tb;
    }

    float cumA[4], cumB[4];
#pragma unroll
    for (int m = 0; m < 4; ++m) cumA[m] = cumb[Tstart + 2 + 8 * m + sl];
    const float x1 = cumb[Tstart + 1] + R - shift;
    float beta = __expf(x1);
    float rbeta = __expf(-x1);

#pragma unroll 1
    for (int lt0 = 1; lt0 <= L; lt0 += 32) {
        if (lt0 + 32 <= L) {
#pragma unroll
            for (int m = 0; m < 4; ++m) {
                int idx = Tstart + lt0 + 33 + 8 * m + sl;
                idx = idx > NT ? NT : idx;
                cumB[m] = cumb[idx];
            }
        }
#pragma unroll 1
        for (int g8 = 0; g8 < 4; ++g8) {
            if (lt0 > 1 || g8 > 0) {
                __syncwarp();
                int eb = (__float_as_int(Et1) >> 23) & 255;
                if (eb == 0) eb = 1;
                int de = eb - 82;
                de = de < -100 ? -100 : (de > 120 ? 120 : de);
                const float sc = __int_as_float((127 - de) << 23);
                const float rsc = __int_as_float((127 + de) << 23);
#pragma unroll
                for (int m = 0; m < 32; ++m) ringc[sl + 8 * m] *= sc;
                Et1 *= sc;
                tailD *= sc;
                R += (float)de * LN2;
                beta *= rsc;
                rbeta *= sc;
                __syncwarp();
            }
            const float cumCur = cumA[g8];
#pragma unroll
            for (int q = 0; q < 8; ++q) {
                const int lt = lt0 + g8 * 8 + q;
                const int t = Tstart + lt;
                const int par = lt & 1;

                const float D = fmaf(Et1, ed1s, tailD);
                const float u = D * beta;        // exp(alpha_c - shift)
                if (sl == 0) u_sm[par][c] = u;
                __syncthreads();

                const float* ub = u_sm[par];
                const float uv0 = ub[3 * sl + 0];
                const float uv1 = ub[3 * sl + 1];
                const float uv2 = ub[3 * sl + 2];
                float w = fmaf(uv2, etr2, fmaf(uv1, etr1, uv0 * etr0));

                const float* pp = ringc + (((t - 1 - 13 * sl) & 127) + 116);
                float ta = pp[12] * edt[0];
                float tb2 = pp[11] * edt[1];
                float tcc = pp[10] * edt[2];
                ta = fmaf(pp[9], edt[3], ta);
                tb2 = fmaf(pp[8], edt[4], tb2);
                tcc = fmaf(pp[7], edt[5], tcc);
                ta = fmaf(pp[6], edt[6], ta);
                tb2 = fmaf(pp[5], edt[7], tb2);
                tcc = fmaf(pp[4], edt[8], tcc);
                ta = fmaf(pp[3], edt[9], ta);
                tb2 = fmaf(pp[2], edt[10], tb2);
                tcc = fmaf(pp[1], edt[11], tcc);
                ta = fmaf(pp[0], edt[12], ta);
                float tb = ta + tb2 + tcc;

#pragma unroll
                for (int off = 4; off > 0; off >>= 1) {
                    w  += __shfl_xor_sync(FULL, w, off);
                    tb += __shfl_xor_sync(FULL, tb, off);
                }

                const float Et = w * rbeta;
                const int slot = t & 127;
                if (sl == 0) {
                    ringc[slot] = Et;
                    ringc[slot + 128] = Et;
                }

                if (lt == MFIX || t == len) {
                    float su = uv0 + uv1 + uv2;
#pragma unroll
                    for (int off = 4; off > 0; off >>= 1)
                        su += __shfl_xor_sync(FULL, su, off);
                    if (tid == 0) {
                        const float val = shift + __logf(fmaxf(su, 1e-37f));
                        if (PHASE == 1) {
                            if (lt == MFIX) g_lsem[b * NCH + p] = val;
                            if (t == len && (p == 0 || lt > MFIX)) {
                                g_outA[b] = val;
                                g_outP[b] = p;
                            }
                        } else {
                            if (lt == MFIX) g_C[b * NCH + p] = val - g_lsem[b * NCH + p];
                            if (t == len) {
                                g_outA[b] = val;
                                g_outP[b] = p - 1;
                            }
                        }
                    }
                }

                const float u0 = __shfl_sync(FULL, uv0, 0);
                int e0 = (__float_as_int(u0) >> 23) & 255;
                int ds = (e0 == 0) ? -30 : (e0 - 127);
                ds = ds < -30 ? -30 : (ds > 30 ? 30 : ds);
                shift = fmaf((float)ds, LN2, shift);

                const float crN = __shfl_sync(FULL, cumCur, laneBase + q) + R;
                const float xn = crN - shift;
                beta = __expf(xn);
                rbeta = __expf(-xn);

                Et1 = Et;
                tailD = tb;
            }
        }
        if (lt0 + 31 >= lenLoc) break;
#pragma unroll
        for (int m = 0; m < 4; ++m) cumA[m] = cumB[m];
    }

    if (PHASE == 1 && p < NCH - 1 && len > Tend) {
        __syncthreads();
        float* dst = g_stateE + (size_t)(b * NCH + p) * NC * 128;
        for (int i = tid; i < NC * 128; i += 192)
            dst[i] = ring[(i >> 7) * RST + (i & 127)];
        if (sl == 0) g_stateR[(b * NCH + p) * NC + c] = R;
        if (tid == 0) g_stateS[b * NCH + p] = shift;
    }
}

// ---------------------------------------------------------------------------
// Kernel 4: prefix the corrections and emit final partitions.
// ---------------------------------------------------------------------------
__global__ void fix_kernel(float* __restrict__ out) {
    const int b = threadIdx.x;
    if (b < NB) {
        float d = 0.f;
        const int P = g_outP[b];
        for (int q = 1; q <= P; ++q) d += g_C[b * NCH + q];
        out[b] = g_outA[b] + d;
    }
}

// ---------------------------------------------------------------------------
extern "C" void kernel_launch(void* const* d_in, const int* in_sizes, int n_in,
                              void* d_out, int out_size) {
    const float* hs    = (const float*)d_in[0];   // [B,T,H]
    const float* W     = (const float*)d_in[1];   // [H,C]
    const float* bias  = (const float*)d_in[2];   // [C]
    const float* trans = (const float*)d_in[3];   // [C,C]
    const float* dur   = (const float*)d_in[4];   // [K,C]
    const int*   len   = (const int*)d_in[5];     // [B]
    float* out = (float*)d_out;

    gemm_kernel<<<(NB * NT) / 1024, 256>>>(hs, W, bias);
    cumsum_kernel<<<NB * NC, 32>>>();
    scan_kernel<1><<<NB * NCH, 192>>>(trans, dur, len);
    scan_kernel<2><<<NB * (NCH - 1), 192>>>(trans, dur, len);
    fix_kernel<<<1, 32>>>(out);
}